// round 13
// baseline (speedup 1.0000x reference)
#include <cuda_runtime.h>

// BoxBlur 13x13 reflect, (8,64,512,512) fp32. Separable, sliding-window.
// = R12 winner (186.7us) with ONE change: pass 1 uses float2 LDG.64 with
//   row-split groups (warps 0-7 rows 0-7, warps 8-15 rows 8-15; each thread
//   owns a column pair). Halves pass-1 LDG instruction count and per-thread
//   dependency chain; all 512 threads stay load-active.

#define Wd 512
#define Hd 512
#define TY 16
#define NT 512
#define PW 513            // vs stride (conflict-free pass-2 access)
#define OW 513            // os stride (conflict-free)
#define KHALF 6

#define SMEM_FLOATS (TY * PW + TY * OW)
#define SMEM_BYTES  (SMEM_FLOATS * 4)       // 65,664 B -> 3 CTAs/SM (197KB)

__device__ __forceinline__ int reflect_i(int i, int n) {
    // jnp.pad 'reflect', pad (6) < n: single fold.
    if (i < 0) i = -i;
    if (i >= n) i = 2 * n - 2 - i;
    return i;
}

__global__ __launch_bounds__(NT, 3)
void boxblur13(const float* __restrict__ in,
               const float* __restrict__ kern,
               float* __restrict__ out) {
    extern __shared__ float sm[];
    float* __restrict__ vs = sm;             // [TY][PW]  vertical 13-sums
    float* __restrict__ os = sm + TY * PW;   // [TY][OW]  output staging

    const int ytile = blockIdx.x;
    const int plane = blockIdx.y;
    const int y0 = ytile * TY;
    const float* __restrict__ ip = in  + (size_t)plane * (Hd * Wd);
    float*       __restrict__ op = out + (size_t)plane * (Hd * Wd);
    const int t = threadIdx.x;               // 0..511
    const float k0 = kern[0];                // 1/169

    // ---- Pass 1: vertical running 13-sum, float2 columns, row-split ----
    // warps 0-7: rows 0-7; warps 8-15: rows 8-15. Thread owns column pair p.
    {
        const int p      = t & 255;          // column pair 0..255
        const int jstart = (t >> 8) * 8;     // 0 or 8
        const float2* __restrict__ ip2 = (const float2*)ip;

        float sx = 0.0f, sy = 0.0f;
        #pragma unroll
        for (int j = -KHALF; j < KHALF; j++) {          // 12 init rows
            const float2 v = ip2[reflect_i(y0 + jstart + j, Hd) * (Wd / 2) + p];
            sx += v.x; sy += v.y;
        }
        #pragma unroll
        for (int j = 0; j < 8; j++) {
            const float2 v = ip2[reflect_i(y0 + jstart + j + KHALF, Hd) * (Wd / 2) + p];
            sx += v.x; sy += v.y;
            vs[(jstart + j) * PW + 2 * p]     = sx;     // 2x scalar STS
            vs[(jstart + j) * PW + 2 * p + 1] = sy;     // (2-way each, same wf/out as R12)
            const float2 u = ip2[reflect_i(y0 + jstart + j - KHALF, Hd) * (Wd / 2) + p];
            sx -= u.x; sy -= u.y;                       // outgoing reload: cache hit
        }
    }
    __syncthreads();   // the ONLY block-wide sync

    // ---- Pass 2 + flush: warp-private 32-column block, all 16 rows ----
    {
        const int lane = t & 31;
        const int w    = t >> 5;        // warp 0..15: columns [32w, 32w+32)
        const int rl   = lane & 15;     // row 0..15
        const int sc   = lane >> 4;     // half-block select
        const int xb   = 32 * w + 16 * sc;
        const float* __restrict__ vrow = vs + rl * PW;
        float* __restrict__ orow = os + rl * OW;

        // ring-free sliding 13-sum over 16 outputs
        float s = 0.0f;
        #pragma unroll
        for (int k = 0; k < 13; k++)
            s += vrow[reflect_i(xb - KHALF + k, Wd)];
        #pragma unroll
        for (int i = 0; i < 16; i++) {
            orow[xb + i] = s * k0;      // STS banks (rl+16sc+i)%32: conflict-free
            s += vrow[reflect_i(xb + i + KHALF + 1, Wd)]
               - vrow[reflect_i(xb + i - KHALF, Wd)];
        }
        __syncwarp();

        // flush own 32-col block: lane = column -> 128B coalesced STG per row
        const int c = 32 * w + lane;
        #pragma unroll
        for (int row = 0; row < TY; row++) {
            op[(size_t)(y0 + row) * Wd + c] = os[row * OW + c];  // LDS banks (row+lane)%32
        }
    }
}

extern "C" void kernel_launch(void* const* d_in, const int* in_sizes, int n_in,
                              void* d_out, int out_size) {
    const float* input  = (const float*)d_in[0];   // (8,64,512,512) fp32
    const float* kernel = (const float*)d_in[1];   // (1,13,13) fp32 uniform
    float* out = (float*)d_out;

    cudaFuncSetAttribute(boxblur13, cudaFuncAttributeMaxDynamicSharedMemorySize,
                         SMEM_BYTES);

    dim3 grid(Hd / TY, 8 * 64);    // (32 y-tiles, 512 planes)
    boxblur13<<<grid, NT, SMEM_BYTES>>>(input, kernel, out);
}